// round 16
// baseline (speedup 1.0000x reference)
#include <cuda_runtime.h>
#include <cuda_fp16.h>
#include <math.h>
#include <stdint.h>

// ---------------- problem constants ----------------
constexpr int BATCH  = 2;
constexpr int SEQ    = 2048;
constexpr int CH     = 1024;
constexpr int FF     = 4096;
constexpr int VOCAB  = 32000;
constexpr int NLAYER = 6;
constexpr int NROWS  = BATCH * SEQ;   // 4096
constexpr int BC     = BATCH * CH;    // 2048 wkv channels
constexpr int WS     = 64;            // wkv segments (measured optimum)
constexpr int WL     = SEQ / WS;      // 32 steps per segment

// fp16 weight pool layout
constexpr size_t CCH = (size_t)CH * CH;
constexpr size_t FCH = (size_t)FF * CH;
constexpr size_t OW_ATTK = 0;
constexpr size_t OW_ATTV = OW_ATTK + 6 * CCH;
constexpr size_t OW_ATTR = OW_ATTV + 6 * CCH;
constexpr size_t OW_ATTO = OW_ATTR + 6 * CCH;
constexpr size_t OW_FK   = OW_ATTO + 6 * CCH;
constexpr size_t OW_FV   = OW_FK   + 6 * FCH;
constexpr size_t OW_FR   = OW_FV   + 6 * FCH;
constexpr size_t OW_HEAD = OW_FR   + 6 * CCH;
constexpr size_t W_TOTAL = OW_HEAD + (size_t)VOCAB * CH;

// ---------------- scratch (device globals) ----------------------------------
__device__ __align__(256) float g_x  [NROWS * CH];
__device__ __align__(256) float g_k  [NROWS * CH];
__device__ __align__(256) float g_v  [NROWS * CH];
__device__ __align__(256) float g_r  [NROWS * CH];
__device__ __align__(256) float g_rr [NROWS * CH];

__device__ __align__(256) __half g_w  [W_TOTAL];
__device__ __align__(256) __half g_xk [NROWS * CH];
__device__ __align__(256) __half g_xv [NROWS * CH];
__device__ __align__(256) __half g_xr [NROWS * CH];
__device__ __align__(256) __half g_gw [NROWS * CH];
__device__ __align__(256) __half g_hh [NROWS * CH];
__device__ __align__(256) __half g_kk [NROWS * FF];

// wkv segment states (local + incoming)
__device__ __align__(256) float g_sa[WS * BC], g_sb[WS * BC], g_sp[WS * BC];
__device__ __align__(256) float g_ia[WS * BC], g_ib[WS * BC], g_ip[WS * BC];

// ---------------- helpers -----------------------------------------------------
__device__ __forceinline__ uint32_t smem_u32(const void* p) {
    uint32_t a;
    asm("{ .reg .u64 t; cvta.to.shared.u64 t, %1; cvt.u32.u64 %0, t; }"
        : "=r"(a) : "l"(p));
    return a;
}
__device__ __forceinline__ void store_h2(__half* __restrict__ H, size_t e,
                                         float v0, float v1) {
    *reinterpret_cast<__half2*>(H + e) = __floats2half2_rn(v0, v1);
}
__device__ __forceinline__ void store_h4(__half* __restrict__ H, size_t e,
                                         float v0, float v1, float v2, float v3) {
    __half2 a = __floats2half2_rn(v0, v1);
    __half2 b = __floats2half2_rn(v2, v3);
    uint2 u;
    u.x = *reinterpret_cast<uint32_t*>(&a);
    u.y = *reinterpret_cast<uint32_t*>(&b);
    *reinterpret_cast<uint2*>(H + e) = u;
}

// ---------------- weight fp32 -> fp16 (single launch, ILP + streaming loads) --
struct CvtJobs {
    const float* src[8];
    __half*      dst[8];
    int          n4[8];
};
__device__ __forceinline__ uint2 cvt4(float4 v) {
    __half2 a = __floats2half2_rn(v.x, v.y);
    __half2 b = __floats2half2_rn(v.z, v.w);
    uint2 u;
    u.x = *reinterpret_cast<uint32_t*>(&a);
    u.y = *reinterpret_cast<uint32_t*>(&b);
    return u;
}
__global__ void cvt_all(CvtJobs jobs)
{
    int seg = blockIdx.y;
    const float4* __restrict__ src = reinterpret_cast<const float4*>(jobs.src[seg]);
    uint2* __restrict__ dst = reinterpret_cast<uint2*>(jobs.dst[seg]);
    const int n4 = jobs.n4[seg];
    const int stride = gridDim.x * 256;
    int i = blockIdx.x * 256 + threadIdx.x;
    // 2-way ILP: two independent streaming loads in flight per iteration
    for (; i + stride < n4; i += 2 * stride) {
        float4 v0 = __ldcs(src + i);
        float4 v1 = __ldcs(src + i + stride);
        dst[i]          = cvt4(v0);
        dst[i + stride] = cvt4(v1);
    }
    if (i < n4) {
        dst[i] = cvt4(__ldcs(src + i));
    }
}

// ---------------- shared GEMM bits --------------------------------------------
enum { EPI_NONE = 0, EPI_RELUSQ = 1, EPI_SIGMOID = 2, EPI_ADD = 3, EPI_ADD_MUL = 4 };

struct GJob {
    const __half *A, *B;
    float* C;
    __half* Ch;
    const float *Res, *Mul;
    int N, K, epi, ntx, base;
};
struct GJobs { GJob j[3]; int njobs; };

__device__ __forceinline__ void cp16(uint32_t dst, const void* src) {
    asm volatile("cp.async.cg.shared.global [%0], [%1], 16;" :: "r"(dst), "l"(src));
}
__device__ __forceinline__ void ldsm4(uint32_t* r, uint32_t addr) {
    asm volatile("ldmatrix.sync.aligned.m8n8.x4.shared.b16 {%0,%1,%2,%3}, [%4];"
                 : "=r"(r[0]), "=r"(r[1]), "=r"(r[2]), "=r"(r[3]) : "r"(addr));
}
__device__ __forceinline__ void mma16816(float* c, const uint32_t* a, const uint32_t* b) {
    asm volatile(
        "mma.sync.aligned.m16n8k16.row.col.f32.f16.f16.f32 "
        "{%0,%1,%2,%3}, {%4,%5,%6,%7}, {%8,%9}, {%0,%1,%2,%3};"
        : "+f"(c[0]), "+f"(c[1]), "+f"(c[2]), "+f"(c[3])
        : "r"(a[0]), "r"(a[1]), "r"(a[2]), "r"(a[3]), "r"(b[0]), "r"(b[1]));
}

// ================= WIDE GEMM: 128x256 tile, 512 threads, 4 stages =============
constexpr int W_ST_A  = 128 * 64 * 2;
constexpr int W_ST_B  = 256 * 64 * 2;
constexpr int W_STAGE = W_ST_A + W_ST_B;       // 49152
constexpr int W_NSTG  = 4;
constexpr int W_SMEM  = W_NSTG * W_STAGE;      // 196608

__global__ void __launch_bounds__(512, 1)
gemm_w(GJobs jobs)
{
    extern __shared__ char smem[];
    const uint32_t sb = smem_u32(smem);

    int id = blockIdx.x;
    int ji = 0;
    if (jobs.njobs > 1 && id >= jobs.j[1].base) ji = 1;
    if (jobs.njobs > 2 && id >= jobs.j[2].base) ji = 2;
    const GJob jb = jobs.j[ji];
    const int local = id - jb.base;
    const int bn = local % jb.ntx;
    const int bm = local / jb.ntx;
    const int N = jb.N, K = jb.K;
    const int nk = K >> 6;

    const int tid  = threadIdx.x;
    const int lane = tid & 31;
    const int w    = tid >> 5;
    const int wr   = w >> 2;
    const int wc   = w & 3;

    const int jj = tid & 7;
    const int rg = tid >> 3;          // 0..63
    const __half* Ag = jb.A + (size_t)bm * 128 * K;
    const __half* Bg = jb.B + (size_t)bn * 256 * K;

    auto issue = [&](int kt, int st) {
        const uint32_t base = sb + (uint32_t)st * W_STAGE;
        const size_t kof = (size_t)kt * 64 + jj * 8;
#pragma unroll
        for (int it = 0; it < 2; it++) {
            int r = rg + it * 64;
            cp16(base + r * 128 + (uint32_t)((jj ^ (r & 7)) << 4),
                 Ag + (size_t)r * K + kof);
        }
#pragma unroll
        for (int it = 0; it < 4; it++) {
            int r = rg + it * 64;
            cp16(base + W_ST_A + r * 128 + (uint32_t)((jj ^ (r & 7)) << 4),
                 Bg + (size_t)r * K + kof);
        }
    };

    const int sel = lane >> 3, r8 = lane & 7;
    uint32_t a_row[2], b_row[4], a_chk[4], b_chk[4];
#pragma unroll
    for (int mt = 0; mt < 2; mt++)
        a_row[mt] = (uint32_t)((wr * 32 + mt * 16 + (sel & 1) * 8 + r8) * 128);
#pragma unroll
    for (int np = 0; np < 4; np++)
        b_row[np] = (uint32_t)((wc * 64 + np * 16 + (sel >> 1) * 8 + r8) * 128);
#pragma unroll
    for (int ks = 0; ks < 4; ks++) {
        a_chk[ks] = (uint32_t)(((ks * 2 + (sel >> 1)) ^ r8) << 4);
        b_chk[ks] = (uint32_t)(((ks * 2 + (sel & 1)) ^ r8) << 4);
    }

    float acc[2][8][4];
#pragma unroll
    for (int mt = 0; mt < 2; mt++)
#pragma unroll
        for (int nt = 0; nt < 8; nt++)
#pragma unroll
            for (int q = 0; q < 4; q++) acc[mt][nt][q] = 0.f;

    auto compute = [&](int st) {
        const uint32_t sbase = sb + (uint32_t)st * W_STAGE;
#pragma unroll
        for (int ks = 0; ks < 4; ks++) {
            uint32_t a[2][4];
#pragma unroll
            for (int mt = 0; mt < 2; mt++)
                ldsm4(a[mt], sbase + a_row[mt] + a_chk[ks]);
            uint32_t b[8][2];
#pragma unroll
            for (int np = 0; np < 4; np++) {
                uint32_t t[4];
                ldsm4(t, sbase + W_ST_A + b_row[np] + b_chk[ks]);
                b[2*np][0]   = t[0]; b[2*np][1]   = t[1];
                b[2*np+1][0] = t[2]; b[2*np+1][1] = t[3];
            }
#pragma unroll
            for (int mt = 0; mt < 2; mt++)
#pragma unroll
                for (int nt = 0; nt < 8; nt++)
                    mma16816(acc[mt][nt], a[mt], b[nt]);
        }
    };

    issue(0, 0);
    asm volatile("cp.async.commit_group;" ::: "memory");
    if (nk > 1) { issue(1, 1); }
    asm volatile("cp.async.commit_group;" ::: "memory");
    if (nk > 2) { issue(2, 2); }
    asm volatile("cp.async.commit_group;" ::: "memory");

    int st = 0;
    for (int kt = 0; kt < nk; kt++) {
        if (kt + 2 < nk) {
            asm volatile("cp.async.wait_group 2;" ::: "memory");
        } else if (kt + 1 < nk) {
            asm volatile("cp.async.wait_group 1;" ::: "memory");
        } else {
            asm volatile("cp.async.wait_group 0;" ::: "memory");
        }
        __syncthreads();
        if (kt + 3 < nk) {
            int ns = st + 3; if (ns >= W_NSTG) ns -= W_NSTG;
            issue(kt + 3, ns);
        }
        asm volatile("cp.async.commit_group;" ::: "memory");
        compute(st);
        st = (st + 1 == W_NSTG) ? 0 : st + 1;
    }

    const int r0    = bm * 128 + wr * 32 + (lane >> 2);
    const int cbase = bn * 256 + wc * 64 + (lane & 3) * 2;
    const int epi = jb.epi;
#pragma unroll
    for (int mt = 0; mt < 2; mt++) {
#pragma unroll
        for (int nt = 0; nt < 8; nt++) {
            int r = r0 + mt * 16;
            int c = cbase + nt * 8;
#pragma unroll
            for (int half = 0; half < 2; half++) {
                int rr2 = r + half * 8;
                float v0 = acc[mt][nt][half * 2 + 0];
                float v1 = acc[mt][nt][half * 2 + 1];
                size_t off = (size_t)rr2 * N + c;
                if (epi == EPI_RELUSQ) {
                    float t0 = v0 > 0.f ? v0 : 0.f; v0 = t0 * t0;
                    float t1 = v1 > 0.f ? v1 : 0.f; v1 = t1 * t1;
                    store_h2(jb.Ch, off, v0, v1);
                } else {
                    if (epi == EPI_SIGMOID) {
                        v0 = 1.f / (1.f + __expf(-v0));
                        v1 = 1.f / (1.f + __expf(-v1));
                    } else if (epi == EPI_ADD) {
                        float2 rv = *(const float2*)(jb.Res + off);
                        v0 += rv.x; v1 += rv.y;
                    } else if (epi == EPI_ADD_MUL) {
                        float2 rv = *(const float2*)(jb.Res + off);
                        float2 mv = *(const float2*)(jb.Mul + off);
                        v0 = rv.x + mv.x * v0; v1 = rv.y + mv.y * v1;
                    }
                    *(float2*)(jb.C + off) = make_float2(v0, v1);
                }
            }
        }
    }
}

// ================= NARROW GEMM: 128x128 tile, 256 threads, 2 CTAs/SM ==========
constexpr int N_ST_A  = 128 * 64 * 2;
constexpr int N_ST_B  = 128 * 64 * 2;
constexpr int N_STAGE = N_ST_A + N_ST_B;       // 32768
constexpr int N_NSTG  = 3;
constexpr int N_SMEM  = N_NSTG * N_STAGE;      // 98304

__global__ void __launch_bounds__(256, 2)
gemm_n(GJobs jobs)
{
    extern __shared__ char smem[];
    const uint32_t sb = smem_u32(smem);

    int id = blockIdx.x;
    int ji = 0;
    if (jobs.njobs > 1 && id >= jobs.j[1].base) ji = 1;
    if (jobs.njobs > 2 && id >= jobs.j[2].base) ji = 2;
    const GJob jb = jobs.j[ji];
    const int local = id - jb.base;
    const int bn = local % jb.ntx;
    const int bm = local / jb.ntx;
    const int N = jb.N, K = jb.K;
    const int nk = K >> 6;

    const int tid  = threadIdx.x;
    const int lane = tid & 31;
    const int w    = tid >> 5;
    const int wr   = w >> 1;
    const int wc   = w & 1;

    const int jj = tid & 7;
    const int rg = tid >> 3;          // 0..31
    const __half* Ag = jb.A + (size_t)bm * 128 * K;
    const __half* Bg = jb.B + (size_t)bn * 128 * K;

    auto issue = [&](int kt, int st) {
        const uint32_t base = sb + (uint32_t)st * N_STAGE;
        const size_t kof = (size_t)kt * 64 + jj * 8;
#pragma unroll
        for (int it = 0; it < 4; it++) {
            int r = rg + it * 32;
            cp16(base + r * 128 + (uint32_t)((jj ^ (r & 7)) << 4),
                 Ag + (size_t)r * K + kof);
        }
#pragma unroll
        for (int it = 0; it < 4; it++) {
            int r = rg + it * 32;
            cp16(base + N_ST_A + r * 128 + (uint32_t)((jj ^ (r & 7)) << 4),
                 Bg + (size_t)r * K + kof);
        }
    };

    const int sel = lane >> 3, r8 = lane & 7;
    uint32_t a_row[2], b_row[4], a_chk[4], b_chk[4];
#pragma unroll
    for (int mt = 0; mt < 2; mt++)
        a_row[mt] = (uint32_t)((wr * 32 + mt * 16 + (sel & 1) * 8 + r8) * 128);
#pragma unroll
    for (int np = 0; np < 4; np++)
        b_row[np] = (uint32_t)((wc * 64 + np * 16 + (sel >> 1) * 8 + r8) * 128);
#pragma unroll
    for (int ks = 0; ks < 4; ks++) {
        a_chk[ks] = (uint32_t)(((ks * 2 + (sel >> 1)) ^ r8) << 4);
        b_chk[ks] = (uint32_t)(((ks * 2 + (sel & 1)) ^ r8) << 4);
    }

    float acc[2][8][4];
#pragma unroll
    for (int mt = 0; mt < 2; mt++)
#pragma unroll
        for (int nt = 0; nt < 8; nt++)
#pragma unroll
            for (int q = 0; q < 4; q++) acc[mt][nt][q] = 0.f;

    auto compute = [&](int st) {
        const uint32_t sbase = sb + (uint32_t)st * N_STAGE;
#pragma unroll
        for (int ks = 0; ks < 4; ks++) {
            uint32_t a[2][4];
#pragma unroll
            for (int mt = 0; mt < 2; mt++)
                ldsm4(a[mt], sbase + a_row[mt] + a_chk[ks]);
            uint32_t b[8][2];
#pragma unroll
            for (int np = 0; np < 4; np++) {
                uint32_t t[4];
                ldsm4(t, sbase + N_ST_A + b_row[np] + b_chk[ks]);
                b[2*np][0]   = t[0]; b[2*np][1]   = t[1];
                b[2*np+1][0] = t[2]; b[2*np+1][1] = t[3];
            }
#pragma unroll
            for (int mt = 0; mt < 2; mt++)
#pragma unroll
                for (int nt = 0; nt < 8; nt++)
                    mma16816(acc[mt][nt], a[mt], b[nt]);
        }
    };

    // R8 schedule (measured best for 2-CTA/SM)
    issue(0, 0);
    asm volatile("cp.async.commit_group;" ::: "memory");
    if (nk > 1) { issue(1, 1); }
    asm volatile("cp.async.commit_group;" ::: "memory");

    int st = 0;
    for (int kt = 0; kt < nk; kt++) {
        if (kt + 1 < nk) {
            asm volatile("cp.async.wait_group 1;" ::: "memory");
        } else {
            asm volatile("cp.async.wait_group 0;" ::: "memory");
        }
        __syncthreads();
        compute(st);
        if (kt + 2 < nk) {
            int ns = st + 2; if (ns >= N_NSTG) ns -= N_NSTG;
            issue(kt + 2, ns);
            asm volatile("cp.async.commit_group;" ::: "memory");
        }
        st = (st + 1 == N_NSTG) ? 0 : st + 1;
    }

    const int r0    = bm * 128 + wr * 32 + (lane >> 2);
    const int cbase = bn * 128 + wc * 64 + (lane & 3) * 2;
    const int epi = jb.epi;
#pragma unroll
    for (int mt = 0; mt < 2; mt++) {
#pragma unroll
        for (int nt = 0; nt < 8; nt++) {
            int r = r0 + mt * 16;
            int c = cbase + nt * 8;
#pragma unroll
            for (int half = 0; half < 2; half++) {
                int rr2 = r + half * 8;
                float v0 = acc[mt][nt][half * 2 + 0];
                float v1 = acc[mt][nt][half * 2 + 1];
                size_t off = (size_t)rr2 * N + c;
                if (epi == EPI_RELUSQ) {
                    float t0 = v0 > 0.f ? v0 : 0.f; v0 = t0 * t0;
                    float t1 = v1 > 0.f ? v1 : 0.f; v1 = t1 * t1;
                    store_h2(jb.Ch, off, v0, v1);
                } else {
                    if (epi == EPI_SIGMOID) {
                        v0 = 1.f / (1.f + __expf(-v0));
                        v1 = 1.f / (1.f + __expf(-v1));
                    } else if (epi == EPI_ADD) {
                        float2 rv = *(const float2*)(jb.Res + off);
                        v0 += rv.x; v1 += rv.y;
                    } else if (epi == EPI_ADD_MUL) {
                        float2 rv = *(const float2*)(jb.Res + off);
                        float2 mv = *(const float2*)(jb.Mul + off);
                        v0 = rv.x + mv.x * v0; v1 = rv.y + mv.y * v1;
                    }
                    *(float2*)(jb.C + off) = make_float2(v0, v1);
                }
            }
        }
    }
}

// ---------------- fused LN + token-shift mix (float4 vectorized) --------------
__device__ __forceinline__ void ln_stats2_v4(float4 vT, float4 vP, bool hasP,
                                             float& mnT, float& invT,
                                             float& mnP, float& invP)
{
    float sT = vT.x + vT.y + vT.z + vT.w;
    float s2T = vT.x * vT.x + vT.y * vT.y + vT.z * vT.z + vT.w * vT.w;
    float sP = 0.f, s2P = 0.f;
    if (hasP) {
        sP = vP.x + vP.y + vP.z + vP.w;
        s2P = vP.x * vP.x + vP.y * vP.y + vP.z * vP.z + vP.w * vP.w;
    }
#pragma unroll
    for (int o = 16; o > 0; o >>= 1) {
        sT  += __shfl_down_sync(0xffffffffu, sT,  o);
        s2T += __shfl_down_sync(0xffffffffu, s2T, o);
        sP  += __shfl_down_sync(0xffffffffu, sP,  o);
        s2P += __shfl_down_sync(0xffffffffu, s2P, o);
    }
    __shared__ float sh[4][8];
    int warp = threadIdx.x >> 5, lane = threadIdx.x & 31;
    if (lane == 0) { sh[0][warp] = sT; sh[1][warp] = s2T; sh[2][warp] = sP; sh[3][warp] = s2P; }
    __syncthreads();
    float tT = 0.f, t2T = 0.f, tP = 0.f, t2P = 0.f;
#pragma unroll
    for (int i = 0; i < 8; i++) {
        tT += sh[0][i]; t2T += sh[1][i]; tP += sh[2][i]; t2P += sh[3][i];
    }
    mnT = tT * (1.f / CH);
    invT = rsqrtf(fmaxf(t2T * (1.f / CH) - mnT * mnT, 0.f) + 1e-5f);
    mnP = tP * (1.f / CH);
    invP = rsqrtf(fmaxf(t2P * (1.f / CH) - mnP * mnP, 0.f) + 1e-5f);
}

__global__ void ln_mix_time(const float* __restrict__ x,
                            const float* __restrict__ w, const float* __restrict__ b,
                            const float* __restrict__ mk, const float* __restrict__ mv,
                            const float* __restrict__ mr,
                            __half* __restrict__ xk, __half* __restrict__ xv,
                            __half* __restrict__ xr)
{
    const int row = blockIdx.x;
    const bool hasP = (row & (SEQ - 1)) != 0;
    const float* xT = x + (size_t)row * CH;
    const float* xP = xT - CH;
    const int i = threadIdx.x * 4;

    float4 vT = *(const float4*)(xT + i);
    float4 vP = hasP ? *(const float4*)(xP + i) : make_float4(0.f, 0.f, 0.f, 0.f);
    float mnT, invT, mnP, invP;
    ln_stats2_v4(vT, vP, hasP, mnT, invT, mnP, invP);

    float4 wv = *(const float4*)(w + i);
    float4 bv = *(const float4*)(b + i);
    float hT[4], hP[4];
    const float* pT = &vT.x; const float* pP = &vP.x;
    const float* pw = &wv.x; const float* pb = &bv.x;
#pragma unroll
    for (int q = 0; q < 4; q++) {
        hT[q] = (pT[q] - mnT) * invT * pw[q] + pb[q];
        hP[q] = hasP ? (pP[q] - mnP) * invP * pw[q] + pb[q] : 0.f;
    }
    const size_t e = (size_t)row * CH + i;
    float4 m;
    const float* pm;
    m = *(const float4*)(mk + i); pm = &m.x;
    store_h4(xk, e, hT[0]*pm[0]+hP[0]*(1.f-pm[0]), hT[1]*pm[1]+hP[1]*(1.f-pm[1]),
                   hT[2]*pm[2]+hP[2]*(1.f-pm[2]), hT[3]*pm[3]+hP[3]*(1.f-pm[3]));
    m = *(const float4*)(mv + i); pm = &m.x;
    store_h4(xv, e, hT[0]*pm[0]+hP[0]*(1.f-pm[0]), hT[1]*pm[1]+hP[1]*(1.f-pm[1]),
                   hT[2]*pm[2]+hP[2]*(1.f-pm[2]), hT[3]*pm[3]+hP[3]*(1.f-pm[3]));
    m = *(const float4*)(mr + i); pm = &m.x;
    store_h4(xr, e, hT[0]*pm[0]+hP[0]*(1.f-pm[0]), hT[1]*pm[1]+hP[1]*(1.f-pm[1]),
                   hT[2]*pm[2]+hP[2]*(1.f-pm[2]), hT[3]*pm[3]+hP[3]*(1.f-pm[3]));
}

__global__ void ln_mix_chan(const float* __restrict__ x,
                            const float* __restrict__ w, const float* __restrict__ b,
                            const float* __restrict__ mk, const float* __restrict__ mr,
                            __half* __restrict__ xk, __half* __restrict__ xr)
{
    const int row = blockIdx.x;
    const bool hasP = (row & (SEQ - 1)) != 0;
    const float* xT = x + (size_t)row * CH;
    const float* xP = xT - CH;
    const int i = threadIdx.x * 4;

    float4 vT = *(const float4*)(xT + i);
    float4 vP = hasP ? *(const float4*)(xP + i) : make_float4(0.f, 0.f, 0.f, 0.f);
    float mnT, invT, mnP, invP;
    ln_stats2_v4(vT, vP, hasP, mnT, invT, mnP, invP);

    float4 wv = *(const float4*)(w + i);
    float4 bv = *(const float4*)(b + i);
    float hT[4], hP[4];
    const float* pT = &vT.x; const float* pP = &vP.x;
    const float* pw = &wv.x; const float* pb = &bv.x;
#pragma unroll
    for (int q = 0; q < 4; q++) {
        hT[q] = (pT[q] - mnT) * invT * pw[q] + pb[q];
        hP[q] = hasP ? (pP[q] - mnP) * invP * pw[q] + pb[q] : 0.f;
    }
    const size_t e = (size_t)row * CH + i;
    float4 m;
    const float* pm;
    m = *(const float4*)(mk + i); pm = &m.x;
    store_h4(xk, e, hT[0]*pm[0]+hP[0]*(1.f-pm[0]), hT[1]*pm[1]+hP[1]*(1.f-pm[1]),
                   hT[2]*pm[2]+hP[2]*(1.f-pm[2]), hT[3]*pm[3]+hP[3]*(1.f-pm[3]));
    m = *(const float4*)(mr + i); pm = &m.x;
    store_h4(xr, e, hT[0]*pm[0]+hP[0]*(1.f-pm[0]), hT[1]*pm[1]+hP[1]*(1.f-pm[1]),
                   hT[2]*pm[2]+hP[2]*(1.f-pm[2]), hT[3]*pm[3]+hP[3]*(1.f-pm[3]));
}

// ---------------- layernorm (embed + final), float4 vectorized ----------------
__device__ __forceinline__ void ln_stats_v4(float4 v, float& mean, float& inv)
{
    float s = v.x + v.y + v.z + v.w;
    float s2 = v.x * v.x + v.y * v.y + v.z * v.z + v.w * v.w;
#pragma unroll
    for (int o = 16; o > 0; o >>= 1) {
        s  += __shfl_down_sync(0xffffffffu, s,  o);
        s2 += __shfl_down_sync(0xffffffffu, s2, o);
    }
    __shared__ float sh[2][8];
    int warp = threadIdx.x >> 5, lane = threadIdx.x & 31;
    if (lane == 0) { sh[0][warp] = s; sh[1][warp] = s2; }
    __syncthreads();
    float tot = 0.f, tot2 = 0.f;
#pragma unroll
    for (int i = 0; i < 8; i++) { tot += sh[0][i]; tot2 += sh[1][i]; }
    mean = tot * (1.f / CH);
    float var = tot2 * (1.f / CH) - mean * mean;
    inv = rsqrtf(fmaxf(var, 0.f) + 1e-5f);
}

__global__ void ln_rows_h(const float* __restrict__ in, __half* __restrict__ oh,
                          const float* __restrict__ w, const float* __restrict__ b)
{
    const size_t row = blockIdx.x;
    const int i = threadIdx.x * 4;
    float4 v = *(const float4*)(in + row * CH + i);
    float mean, inv;
    ln_stats_v4(v, mean, inv);
    float4 wv = *(const float4*)(w + i);
    float4 bv = *(const float4*)(b + i);
    store_h4(oh, row * CH + i,
             (v.x - mean) * inv * wv.x + bv.x,
             (v.y - mean) * inv * wv.y + bv.y,
             (v.z - mean) * inv * wv.z + bv.z,
             (v.w - mean) * inv * wv.w + bv.w);
}

__global__ void embed_ln0(const int* __restrict__ idx, const float* __restrict__ emb,
                          const float* __restrict__ w, const float* __restrict__ b,
                          float* __restrict__ out)
{
    int tok = idx[blockIdx.x];
    const int i = threadIdx.x * 4;
    float4 v = *(const float4*)(emb + (size_t)tok * CH + i);
    float mean, inv;
    ln_stats_v4(v, mean, inv);
    float4 wv = *(const float4*)(w + i);
    float4 bv = *(const float4*)(b + i);
    float4 o;
    o.x = (v.x - mean) * inv * wv.x + bv.x;
    o.y = (v.y - mean) * inv * wv.y + bv.y;
    o.z = (v.z - mean) * inv * wv.z + bv.z;
    o.w = (v.w - mean) * inv * wv.w + bv.w;
    *(float4*)(out + (size_t)blockIdx.x * CH + i) = o;
}

// ================= segmented WKV (3 passes) ===================================
__global__ void wkv_p1(const float* __restrict__ td,
                       const float* __restrict__ k, const float* __restrict__ v)
{
    int gid = blockIdx.x * 256 + threadIdx.x;
    if (gid >= WS * BC) return;
    int c  = gid % CH;
    int bs = gid / CH;
    int b  = bs & (BATCH - 1);
    int s  = bs / BATCH;
    float w = -__expf(td[c]);
    const float* kp = k + ((size_t)b * SEQ + (size_t)s * WL) * CH + c;
    const float* vp = v + ((size_t)b * SEQ + (size_t)s * WL) * CH + c;
    float a = 0.f, bb = 0.f, p = -1e38f;
#pragma unroll 4
    for (int t = 0; t < WL; t++) {
        float kt = kp[(size_t)t * CH];
        float vt = vp[(size_t)t * CH];
        float ww2 = p + w;
        float q2  = fmaxf(ww2, kt);
        float e1  = __expf(ww2 - q2);
        float e2  = __expf(kt - q2);
        a  = e1 * a  + e2 * vt;
        bb = e1 * bb + e2;
        p  = q2;
    }
    int slot = s * BC + b * CH + c;
    g_sa[slot] = a; g_sb[slot] = bb; g_sp[slot] = p;
}

__global__ void wkv_p2(const float* __restrict__ td)
{
    int gid = blockIdx.x * 256 + threadIdx.x;
    if (gid >= BC) return;
    int c = gid % CH;
    float w  = -__expf(td[c]);
    float wL = w * (float)WL;
    float a = 0.f, bb = 0.f, p = -1e38f;
    for (int s = 0; s < WS; s++) {
        int slot = s * BC + gid;
        g_ia[slot] = a; g_ib[slot] = bb; g_ip[slot] = p;
        float pin = p + wL;
        float pl = g_sp[slot];
        float pn = fmaxf(pin, pl);
        float e1 = __expf(pin - pn);
        float e2 = __expf(pl - pn);
        a  = e1 * a  + e2 * g_sa[slot];
        bb = e1 * bb + e2 * g_sb[slot];
        p  = pn;
    }
}

__global__ void wkv_p3(const float* __restrict__ td, const float* __restrict__ tf,
                       const float* __restrict__ k, const float* __restrict__ v,
                       const float* __restrict__ r, __half* __restrict__ gw)
{
    int gid = blockIdx.x * 256 + threadIdx.x;
    if (gid >= WS * BC) return;
    int c  = gid % CH;
    int bs = gid / CH;
    int b  = bs & (BATCH - 1);
    int s  = bs / BATCH;
    float w = -__expf(td[c]);
    float u = tf[c];
    const size_t base = ((size_t)b * SEQ + (size_t)s * WL) * CH + c;
    const float* kp = k + base;
    const float* vp = v + base;
    const float* rp = r + base;
    __half*      yp = gw + base;
    int slot = s * BC + b * CH + c;
    float a = g_ia[slot], bb = g_ib[slot], p = g_ip[slot];
#pragma unroll 4
    for (int t = 0; t < WL; t++) {
        float kt = kp[(size_t)t * CH];
        float vt = vp[(size_t)t * CH];
        float rt = rp[(size_t)t * CH];
        float ww = u + kt;
        float q  = fmaxf(p, ww);
        float e1 = __expf(p - q);
        float e2 = __expf(ww - q);
        float y  = (e1 * a + e2 * vt) / (e1 * bb + e2);
        yp[(size_t)t * CH] = __float2half_rn(y / (1.f + __expf(-rt)));
        float ww2 = p + w;
        float q2  = fmaxf(ww2, kt);
        float e1b = __expf(ww2 - q2);
        float e2b = __expf(kt - q2);
        a  = e1b * a  + e2b * vt;
        bb = e1b * bb + e2b;
        p  = q2;
    }
}

// ---------------- host orchestration ------------------------------------------
static GJob mkjob(const __half* A, const __half* B, float* C, __half* Ch,
                  const float* Res, const float* Mul, int N, int K,
                  int epi, int base, int tileN)
{
    GJob j;
    j.A = A; j.B = B; j.C = C; j.Ch = Ch; j.Res = Res; j.Mul = Mul;
    j.N = N; j.K = K; j.epi = epi; j.ntx = N / tileN; j.base = base;
    return j;
}

extern "C" void kernel_launch(void* const* d_in, const int* in_sizes, int n_in,
                              void* d_out, int out_size)
{
    (void)in_sizes; (void)n_in; (void)out_size;

    const int*   idx        = (const int*)  d_in[0];
    const float* emb        = (const float*)d_in[1];
    const float* ln0_w      = (const float*)d_in[2];
    const float* ln0_b      = (const float*)d_in[3];
    const float* ln1_w      = (const float*)d_in[4];
    const float* ln1_b      = (const float*)d_in[5];
    const float* ln2_w      = (const float*)d_in[6];
    const float* ln2_b      = (const float*)d_in[7];
    const float* time_decay = (const float*)d_in[8];
    const float* time_first = (const float*)d_in[9];
    const float* tmk        = (const float*)d_in[10];
    const float* tmv        = (const float*)d_in[11];
    const float* tmr        = (const float*)d_in[12];
    const float* att_Wk     = (const float*)d_in[13];
    const float* att_Wv     = (const float*)d_in[14];
    const float* att_Wr     = (const float*)d_in[15];
    const float* att_Wo     = (const float*)d_in[16];
    const float* fmk        = (const float*)d_in[17];
    const float* fmr        = (const float*)d_in[18];
    const float* ffn_Wk     = (const float*)d_in[19];
    const float* ffn_Wr     = (const float*)d_in[20];
    const float* ffn_Wv     = (const float*)d_in[21];
    const float* ln_out_w   = (const float*)d_in[22];
    const float* ln_out_b   = (const float*)d_in[23];
    const float* head_w     = (const float*)d_in[24];
    float* out = (float*)d_out;

    cudaFuncSetAttribute(gemm_w, cudaFuncAttributeMaxDynamicSharedMemorySize, W_SMEM);
    cudaFuncSetAttribute(gemm_n, cudaFuncAttributeMaxDynamicSharedMemorySize, N_SMEM);

    float *x, *kb, *vb, *rb, *rrb;
    cudaGetSymbolAddress((void**)&x,    g_x);
    cudaGetSymbolAddress((void**)&kb,   g_k);
    cudaGetSymbolAddress((void**)&vb,   g_v);
    cudaGetSymbolAddress((void**)&rb,   g_r);
    cudaGetSymbolAddress((void**)&rrb,  g_rr);

    __half *wp, *xk, *xv, *xr, *gw, *hh, *kk;
    cudaGetSymbolAddress((void**)&wp, g_w);
    cudaGetSymbolAddress((void**)&xk, g_xk);
    cudaGetSymbolAddress((void**)&xv, g_xv);
    cudaGetSymbolAddress((void**)&xr, g_xr);
    cudaGetSymbolAddress((void**)&gw, g_gw);
    cudaGetSymbolAddress((void**)&hh, g_hh);
    cudaGetSymbolAddress((void**)&kk, g_kk);

    // ---- single-launch weight conversion ----
    {
        CvtJobs cj;
        cj.src[0] = att_Wk; cj.dst[0] = wp + OW_ATTK; cj.n4[0] = (int)(6 * CCH / 4);
        cj.src[1] = att_Wv; cj.dst[1] = wp + OW_ATTV; cj.n4[1] = (int)(6 * CCH / 4);
        cj.src[2] = att_Wr; cj.dst[2] = wp + OW_ATTR; cj.n4[2] = (int)(6 * CCH / 4);
        cj.src[3] = att_Wo; cj.dst[3] = wp + OW_ATTO; cj.n4[3] = (int)(6 * CCH / 4);
        cj.src[4] = ffn_Wk; cj.dst[4] = wp + OW_FK;   cj.n4[4] = (int)(6 * FCH / 4);
        cj.src[5] = ffn_Wv; cj.dst[5] = wp + OW_FV;   cj.n4[5] = (int)(6 * FCH / 4);
        cj.src[6] = ffn_Wr; cj.dst[6] = wp + OW_FR;   cj.n4[6] = (int)(6 * CCH / 4);
        cj.src[7] = head_w; cj.dst[7] = wp + OW_HEAD; cj.n4[7] = (int)((size_t)VOCAB * CH / 4);
        dim3 g(1024, 8);
        cvt_all<<<g, 256>>>(cj);
    }

    const int TN_CC = (NROWS / 128) * (CH / 128);   // 256 narrow tiles
    const int TW_FF = (NROWS / 128) * (FF / 256);   // 512 wide tiles
    const int TW_CC = (NROWS / 128) * (CH / 256);   // 128 wide tiles

    embed_ln0<<<NROWS, 256>>>(idx, emb, ln0_w, ln0_b, x);

    for (int i = 0; i < NLAYER; i++) {
        size_t oc = (size_t)i * CH;
        const __half* Wk = wp + OW_ATTK + (size_t)i * CCH;
        const __half* Wv = wp + OW_ATTV + (size_t)i * CCH;
        const __half* Wr = wp + OW_ATTR + (size_t)i * CCH;
        const __half* Wo = wp + OW_ATTO + (size_t)i * CCH;
        const __half* Fk = wp + OW_FK   + (size_t)i * FCH;
        const __half* Fv = wp + OW_FV   + (size_t)i * FCH;
        const __half* Fr = wp + OW_FR   + (size_t)i * CCH;

        // ---- TimeMix ----
        ln_mix_time<<<NROWS, 256>>>(x, ln1_w + oc, ln1_b + oc,
                                    tmk + oc, tmv + oc, tmr + oc, xk, xv, xr);
        {
            GJobs j;
            j.njobs = 3;
            j.j[0] = mkjob(xk, Wk, kb, nullptr, nullptr, nullptr, CH, CH, EPI_NONE, 0, 128);
            j.j[1] = mkjob(xv, Wv, vb, nullptr, nullptr, nullptr, CH, CH, EPI_NONE, TN_CC, 128);
            j.j[2] = mkjob(xr, Wr, rb, nullptr, nullptr, nullptr, CH, CH, EPI_NONE, 2 * TN_CC, 128);
            gemm_n<<<3 * TN_CC, 256, N_SMEM>>>(j);
        }
        wkv_p1<<<WS * BC / 256, 256>>>(time_decay + oc, kb, vb);
        wkv_p2<<<BC / 256, 256>>>(time_decay + oc);
        wkv_p3<<<WS * BC / 256, 256>>>(time_decay + oc, time_first + oc, kb, vb, rb, gw);
        {
            GJobs j;
            j.njobs = 1;
            j.j[0] = mkjob(gw, Wo, x, nullptr, x, nullptr, CH, CH, EPI_ADD, 0, 128);
            gemm_n<<<TN_CC, 256, N_SMEM>>>(j);
        }

        // ---- ChannelMix ----
        ln_mix_chan<<<NROWS, 256>>>(x, ln2_w + oc, ln2_b + oc, fmk + oc, fmr + oc, xk, xr);
        {
            GJobs j;
            j.njobs = 2;
            j.j[0] = mkjob(xk, Fk, nullptr, kk, nullptr, nullptr, FF, CH, EPI_RELUSQ, 0, 256);
            j.j[1] = mkjob(xr, Fr, rrb, nullptr, nullptr, nullptr, CH, CH, EPI_SIGMOID, TW_FF, 256);
            gemm_w<<<TW_FF + TW_CC, 512, W_SMEM>>>(j);
        }
        {
            GJobs j;
            j.njobs = 1;
            j.j[0] = mkjob(kk, Fv, x, nullptr, x, rrb, CH, FF, EPI_ADD_MUL, 0, 128);
            gemm_n<<<TN_CC, 256, N_SMEM>>>(j);
        }
    }

    // final LN + head projection (wide tiles)
    ln_rows_h<<<NROWS, 256>>>(x, hh, ln_out_w, ln_out_b);
    {
        GJobs j;
        j.njobs = 1;
        j.j[0] = mkjob(hh, wp + OW_HEAD, out, nullptr, nullptr, nullptr,
                       VOCAB, CH, EPI_NONE, 0, 256);
        gemm_w<<<(NROWS / 128) * (VOCAB / 256), 512, W_SMEM>>>(j);
    }
}

// round 17
// speedup vs baseline: 1.0349x; 1.0349x over previous
#include <cuda_runtime.h>
#include <cuda_fp16.h>
#include <math.h>
#include <stdint.h>

// ---------------- problem constants ----------------
constexpr int BATCH  = 2;
constexpr int SEQ    = 2048;
constexpr int CH     = 1024;
constexpr int FF     = 4096;
constexpr int VOCAB  = 32000;
constexpr int NLAYER = 6;
constexpr int NROWS  = BATCH * SEQ;   // 4096
constexpr int BC     = BATCH * CH;    // 2048 wkv channels
constexpr int WS     = 64;            // wkv segments (measured optimum)
constexpr int WL     = SEQ / WS;      // 32 steps per segment

// fp16 weight pool layout
constexpr size_t CCH = (size_t)CH * CH;
constexpr size_t FCH = (size_t)FF * CH;
constexpr size_t OW_ATTK = 0;
constexpr size_t OW_ATTV = OW_ATTK + 6 * CCH;
constexpr size_t OW_ATTR = OW_ATTV + 6 * CCH;
constexpr size_t OW_ATTO = OW_ATTR + 6 * CCH;
constexpr size_t OW_FK   = OW_ATTO + 6 * CCH;
constexpr size_t OW_FV   = OW_FK   + 6 * FCH;
constexpr size_t OW_FR   = OW_FV   + 6 * FCH;
constexpr size_t OW_HEAD = OW_FR   + 6 * CCH;
constexpr size_t W_TOTAL = OW_HEAD + (size_t)VOCAB * CH;

// ---------------- scratch (device globals) ----------------------------------
__device__ __align__(256) float g_x  [NROWS * CH];
__device__ __align__(256) float g_k  [NROWS * CH];
__device__ __align__(256) float g_v  [NROWS * CH];
__device__ __align__(256) float g_r  [NROWS * CH];
__device__ __align__(256) float g_rr [NROWS * CH];

__device__ __align__(256) __half g_w  [W_TOTAL];
__device__ __align__(256) __half g_xk [NROWS * CH];
__device__ __align__(256) __half g_xv [NROWS * CH];
__device__ __align__(256) __half g_xr [NROWS * CH];
__device__ __align__(256) __half g_gw [NROWS * CH];
__device__ __align__(256) __half g_hh [NROWS * CH];
__device__ __align__(256) __half g_kk [NROWS * FF];

// wkv segment states (local + incoming)
__device__ __align__(256) float g_sa[WS * BC], g_sb[WS * BC], g_sp[WS * BC];
__device__ __align__(256) float g_ia[WS * BC], g_ib[WS * BC], g_ip[WS * BC];

// ---------------- helpers -----------------------------------------------------
__device__ __forceinline__ uint32_t smem_u32(const void* p) {
    uint32_t a;
    asm("{ .reg .u64 t; cvta.to.shared.u64 t, %1; cvt.u32.u64 %0, t; }"
        : "=r"(a) : "l"(p));
    return a;
}
__device__ __forceinline__ void store_h2(__half* __restrict__ H, size_t e,
                                         float v0, float v1) {
    *reinterpret_cast<__half2*>(H + e) = __floats2half2_rn(v0, v1);
}
__device__ __forceinline__ void store_h4(__half* __restrict__ H, size_t e,
                                         float v0, float v1, float v2, float v3) {
    __half2 a = __floats2half2_rn(v0, v1);
    __half2 b = __floats2half2_rn(v2, v3);
    uint2 u;
    u.x = *reinterpret_cast<uint32_t*>(&a);
    u.y = *reinterpret_cast<uint32_t*>(&b);
    *reinterpret_cast<uint2*>(H + e) = u;
}

// ---------------- weight fp32 -> fp16 (single launch) -------------------------
struct CvtJobs {
    const float* src[8];
    __half*      dst[8];
    int          n4[8];
};
__global__ void cvt_all(CvtJobs jobs)
{
    int seg = blockIdx.y;
    const float* src = jobs.src[seg];
    __half* dst = jobs.dst[seg];
    int n4 = jobs.n4[seg];
    for (int i = blockIdx.x * 256 + threadIdx.x; i < n4; i += gridDim.x * 256) {
        float4 v = reinterpret_cast<const float4*>(src)[i];
        __half2 a = __floats2half2_rn(v.x, v.y);
        __half2 b = __floats2half2_rn(v.z, v.w);
        uint2 u;
        u.x = *reinterpret_cast<uint32_t*>(&a);
        u.y = *reinterpret_cast<uint32_t*>(&b);
        reinterpret_cast<uint2*>(dst)[i] = u;
    }
}

// ---------------- shared GEMM bits --------------------------------------------
enum { EPI_NONE = 0, EPI_RELUSQ = 1, EPI_SIGMOID = 2, EPI_ADD = 3, EPI_ADD_MUL = 4 };

struct GJob {
    const __half *A, *B;
    float* C;
    __half* Ch;
    const float *Res, *Mul;
    int N, K, epi, ntx, base;
};
struct GJobs { GJob j[3]; int njobs; };

__device__ __forceinline__ void cp16(uint32_t dst, const void* src) {
    asm volatile("cp.async.cg.shared.global [%0], [%1], 16;" :: "r"(dst), "l"(src));
}
__device__ __forceinline__ void ldsm4(uint32_t* r, uint32_t addr) {
    asm volatile("ldmatrix.sync.aligned.m8n8.x4.shared.b16 {%0,%1,%2,%3}, [%4];"
                 : "=r"(r[0]), "=r"(r[1]), "=r"(r[2]), "=r"(r[3]) : "r"(addr));
}
__device__ __forceinline__ void mma16816(float* c, const uint32_t* a, const uint32_t* b) {
    asm volatile(
        "mma.sync.aligned.m16n8k16.row.col.f32.f16.f16.f32 "
        "{%0,%1,%2,%3}, {%4,%5,%6,%7}, {%8,%9}, {%0,%1,%2,%3};"
        : "+f"(c[0]), "+f"(c[1]), "+f"(c[2]), "+f"(c[3])
        : "r"(a[0]), "r"(a[1]), "r"(a[2]), "r"(a[3]), "r"(b[0]), "r"(b[1]));
}

// ================= WIDE GEMM: 128x256 tile, 512 threads, 4 stages =============
constexpr int W_ST_A  = 128 * 64 * 2;
constexpr int W_ST_B  = 256 * 64 * 2;
constexpr int W_STAGE = W_ST_A + W_ST_B;       // 49152
constexpr int W_NSTG  = 4;
constexpr int W_SMEM  = W_NSTG * W_STAGE;      // 196608

__global__ void __launch_bounds__(512, 1)
gemm_w(GJobs jobs)
{
    extern __shared__ char smem[];
    const uint32_t sb = smem_u32(smem);

    int id = blockIdx.x;
    int ji = 0;
    if (jobs.njobs > 1 && id >= jobs.j[1].base) ji = 1;
    if (jobs.njobs > 2 && id >= jobs.j[2].base) ji = 2;
    const GJob jb = jobs.j[ji];
    const int local = id - jb.base;
    const int bn = local % jb.ntx;
    const int bm = local / jb.ntx;
    const int N = jb.N, K = jb.K;
    const int nk = K >> 6;

    const int tid  = threadIdx.x;
    const int lane = tid & 31;
    const int w    = tid >> 5;
    const int wr   = w >> 2;
    const int wc   = w & 3;

    const int jj = tid & 7;
    const int rg = tid >> 3;          // 0..63
    const __half* Ag = jb.A + (size_t)bm * 128 * K;
    const __half* Bg = jb.B + (size_t)bn * 256 * K;

    auto issue = [&](int kt, int st) {
        const uint32_t base = sb + (uint32_t)st * W_STAGE;
        const size_t kof = (size_t)kt * 64 + jj * 8;
#pragma unroll
        for (int it = 0; it < 2; it++) {
            int r = rg + it * 64;
            cp16(base + r * 128 + (uint32_t)((jj ^ (r & 7)) << 4),
                 Ag + (size_t)r * K + kof);
        }
#pragma unroll
        for (int it = 0; it < 4; it++) {
            int r = rg + it * 64;
            cp16(base + W_ST_A + r * 128 + (uint32_t)((jj ^ (r & 7)) << 4),
                 Bg + (size_t)r * K + kof);
        }
    };

    const int sel = lane >> 3, r8 = lane & 7;
    uint32_t a_row[2], b_row[4], a_chk[4], b_chk[4];
#pragma unroll
    for (int mt = 0; mt < 2; mt++)
        a_row[mt] = (uint32_t)((wr * 32 + mt * 16 + (sel & 1) * 8 + r8) * 128);
#pragma unroll
    for (int np = 0; np < 4; np++)
        b_row[np] = (uint32_t)((wc * 64 + np * 16 + (sel >> 1) * 8 + r8) * 128);
#pragma unroll
    for (int ks = 0; ks < 4; ks++) {
        a_chk[ks] = (uint32_t)(((ks * 2 + (sel >> 1)) ^ r8) << 4);
        b_chk[ks] = (uint32_t)(((ks * 2 + (sel & 1)) ^ r8) << 4);
    }

    float acc[2][8][4];
#pragma unroll
    for (int mt = 0; mt < 2; mt++)
#pragma unroll
        for (int nt = 0; nt < 8; nt++)
#pragma unroll
            for (int q = 0; q < 4; q++) acc[mt][nt][q] = 0.f;

    auto compute = [&](int st) {
        const uint32_t sbase = sb + (uint32_t)st * W_STAGE;
#pragma unroll
        for (int ks = 0; ks < 4; ks++) {
            uint32_t a[2][4];
#pragma unroll
            for (int mt = 0; mt < 2; mt++)
                ldsm4(a[mt], sbase + a_row[mt] + a_chk[ks]);
            uint32_t b[8][2];
#pragma unroll
            for (int np = 0; np < 4; np++) {
                uint32_t t[4];
                ldsm4(t, sbase + W_ST_A + b_row[np] + b_chk[ks]);
                b[2*np][0]   = t[0]; b[2*np][1]   = t[1];
                b[2*np+1][0] = t[2]; b[2*np+1][1] = t[3];
            }
#pragma unroll
            for (int mt = 0; mt < 2; mt++)
#pragma unroll
                for (int nt = 0; nt < 8; nt++)
                    mma16816(acc[mt][nt], a[mt], b[nt]);
        }
    };

    issue(0, 0);
    asm volatile("cp.async.commit_group;" ::: "memory");
    if (nk > 1) { issue(1, 1); }
    asm volatile("cp.async.commit_group;" ::: "memory");
    if (nk > 2) { issue(2, 2); }
    asm volatile("cp.async.commit_group;" ::: "memory");

    int st = 0;
    for (int kt = 0; kt < nk; kt++) {
        if (kt + 2 < nk) {
            asm volatile("cp.async.wait_group 2;" ::: "memory");
        } else if (kt + 1 < nk) {
            asm volatile("cp.async.wait_group 1;" ::: "memory");
        } else {
            asm volatile("cp.async.wait_group 0;" ::: "memory");
        }
        __syncthreads();
        if (kt + 3 < nk) {
            int ns = st + 3; if (ns >= W_NSTG) ns -= W_NSTG;
            issue(kt + 3, ns);
        }
        asm volatile("cp.async.commit_group;" ::: "memory");
        compute(st);
        st = (st + 1 == W_NSTG) ? 0 : st + 1;
    }

    const int r0    = bm * 128 + wr * 32 + (lane >> 2);
    const int cbase = bn * 256 + wc * 64 + (lane & 3) * 2;
    const int epi = jb.epi;
#pragma unroll
    for (int mt = 0; mt < 2; mt++) {
#pragma unroll
        for (int nt = 0; nt < 8; nt++) {
            int r = r0 + mt * 16;
            int c = cbase + nt * 8;
#pragma unroll
            for (int half = 0; half < 2; half++) {
                int rr2 = r + half * 8;
                float v0 = acc[mt][nt][half * 2 + 0];
                float v1 = acc[mt][nt][half * 2 + 1];
                size_t off = (size_t)rr2 * N + c;
                if (epi == EPI_RELUSQ) {
                    float t0 = v0 > 0.f ? v0 : 0.f; v0 = t0 * t0;
                    float t1 = v1 > 0.f ? v1 : 0.f; v1 = t1 * t1;
                    store_h2(jb.Ch, off, v0, v1);
                } else {
                    if (epi == EPI_SIGMOID) {
                        v0 = 1.f / (1.f + __expf(-v0));
                        v1 = 1.f / (1.f + __expf(-v1));
                    } else if (epi == EPI_ADD) {
                        float2 rv = *(const float2*)(jb.Res + off);
                        v0 += rv.x; v1 += rv.y;
                    } else if (epi == EPI_ADD_MUL) {
                        float2 rv = *(const float2*)(jb.Res + off);
                        float2 mv = *(const float2*)(jb.Mul + off);
                        v0 = rv.x + mv.x * v0; v1 = rv.y + mv.y * v1;
                    }
                    *(float2*)(jb.C + off) = make_float2(v0, v1);
                }
            }
        }
    }
}

// ================= NARROW GEMM: 128x128 tile, 256 threads, 2 CTAs/SM ==========
constexpr int N_ST_A  = 128 * 64 * 2;
constexpr int N_ST_B  = 128 * 64 * 2;
constexpr int N_STAGE = N_ST_A + N_ST_B;       // 32768
constexpr int N_NSTG  = 3;
constexpr int N_SMEM  = N_NSTG * N_STAGE;      // 98304

__global__ void __launch_bounds__(256, 2)
gemm_n(GJobs jobs)
{
    extern __shared__ char smem[];
    const uint32_t sb = smem_u32(smem);

    int id = blockIdx.x;
    int ji = 0;
    if (jobs.njobs > 1 && id >= jobs.j[1].base) ji = 1;
    if (jobs.njobs > 2 && id >= jobs.j[2].base) ji = 2;
    const GJob jb = jobs.j[ji];
    const int local = id - jb.base;
    const int bn = local % jb.ntx;
    const int bm = local / jb.ntx;
    const int N = jb.N, K = jb.K;
    const int nk = K >> 6;

    const int tid  = threadIdx.x;
    const int lane = tid & 31;
    const int w    = tid >> 5;
    const int wr   = w >> 1;
    const int wc   = w & 1;

    const int jj = tid & 7;
    const int rg = tid >> 3;          // 0..31
    const __half* Ag = jb.A + (size_t)bm * 128 * K;
    const __half* Bg = jb.B + (size_t)bn * 128 * K;

    auto issue = [&](int kt, int st) {
        const uint32_t base = sb + (uint32_t)st * N_STAGE;
        const size_t kof = (size_t)kt * 64 + jj * 8;
#pragma unroll
        for (int it = 0; it < 4; it++) {
            int r = rg + it * 32;
            cp16(base + r * 128 + (uint32_t)((jj ^ (r & 7)) << 4),
                 Ag + (size_t)r * K + kof);
        }
#pragma unroll
        for (int it = 0; it < 4; it++) {
            int r = rg + it * 32;
            cp16(base + N_ST_A + r * 128 + (uint32_t)((jj ^ (r & 7)) << 4),
                 Bg + (size_t)r * K + kof);
        }
    };

    const int sel = lane >> 3, r8 = lane & 7;
    uint32_t a_row[2], b_row[4], a_chk[4], b_chk[4];
#pragma unroll
    for (int mt = 0; mt < 2; mt++)
        a_row[mt] = (uint32_t)((wr * 32 + mt * 16 + (sel & 1) * 8 + r8) * 128);
#pragma unroll
    for (int np = 0; np < 4; np++)
        b_row[np] = (uint32_t)((wc * 64 + np * 16 + (sel >> 1) * 8 + r8) * 128);
#pragma unroll
    for (int ks = 0; ks < 4; ks++) {
        a_chk[ks] = (uint32_t)(((ks * 2 + (sel >> 1)) ^ r8) << 4);
        b_chk[ks] = (uint32_t)(((ks * 2 + (sel & 1)) ^ r8) << 4);
    }

    float acc[2][8][4];
#pragma unroll
    for (int mt = 0; mt < 2; mt++)
#pragma unroll
        for (int nt = 0; nt < 8; nt++)
#pragma unroll
            for (int q = 0; q < 4; q++) acc[mt][nt][q] = 0.f;

    auto compute = [&](int st) {
        const uint32_t sbase = sb + (uint32_t)st * N_STAGE;
#pragma unroll
        for (int ks = 0; ks < 4; ks++) {
            uint32_t a[2][4];
#pragma unroll
            for (int mt = 0; mt < 2; mt++)
                ldsm4(a[mt], sbase + a_row[mt] + a_chk[ks]);
            uint32_t b[8][2];
#pragma unroll
            for (int np = 0; np < 4; np++) {
                uint32_t t[4];
                ldsm4(t, sbase + N_ST_A + b_row[np] + b_chk[ks]);
                b[2*np][0]   = t[0]; b[2*np][1]   = t[1];
                b[2*np+1][0] = t[2]; b[2*np+1][1] = t[3];
            }
#pragma unroll
            for (int mt = 0; mt < 2; mt++)
#pragma unroll
                for (int nt = 0; nt < 8; nt++)
                    mma16816(acc[mt][nt], a[mt], b[nt]);
        }
    };

    // R8 schedule (measured best for 2-CTA/SM)
    issue(0, 0);
    asm volatile("cp.async.commit_group;" ::: "memory");
    if (nk > 1) { issue(1, 1); }
    asm volatile("cp.async.commit_group;" ::: "memory");

    int st = 0;
    for (int kt = 0; kt < nk; kt++) {
        if (kt + 1 < nk) {
            asm volatile("cp.async.wait_group 1;" ::: "memory");
        } else {
            asm volatile("cp.async.wait_group 0;" ::: "memory");
        }
        __syncthreads();
        compute(st);
        if (kt + 2 < nk) {
            int ns = st + 2; if (ns >= N_NSTG) ns -= N_NSTG;
            issue(kt + 2, ns);
            asm volatile("cp.async.commit_group;" ::: "memory");
        }
        st = (st + 1 == N_NSTG) ? 0 : st + 1;
    }

    const int r0    = bm * 128 + wr * 32 + (lane >> 2);
    const int cbase = bn * 128 + wc * 64 + (lane & 3) * 2;
    const int epi = jb.epi;
#pragma unroll
    for (int mt = 0; mt < 2; mt++) {
#pragma unroll
        for (int nt = 0; nt < 8; nt++) {
            int r = r0 + mt * 16;
            int c = cbase + nt * 8;
#pragma unroll
            for (int half = 0; half < 2; half++) {
                int rr2 = r + half * 8;
                float v0 = acc[mt][nt][half * 2 + 0];
                float v1 = acc[mt][nt][half * 2 + 1];
                size_t off = (size_t)rr2 * N + c;
                if (epi == EPI_RELUSQ) {
                    float t0 = v0 > 0.f ? v0 : 0.f; v0 = t0 * t0;
                    float t1 = v1 > 0.f ? v1 : 0.f; v1 = t1 * t1;
                    store_h2(jb.Ch, off, v0, v1);
                } else {
                    if (epi == EPI_SIGMOID) {
                        v0 = 1.f / (1.f + __expf(-v0));
                        v1 = 1.f / (1.f + __expf(-v1));
                    } else if (epi == EPI_ADD) {
                        float2 rv = *(const float2*)(jb.Res + off);
                        v0 += rv.x; v1 += rv.y;
                    } else if (epi == EPI_ADD_MUL) {
                        float2 rv = *(const float2*)(jb.Res + off);
                        float2 mv = *(const float2*)(jb.Mul + off);
                        v0 = rv.x + mv.x * v0; v1 = rv.y + mv.y * v1;
                    }
                    *(float2*)(jb.C + off) = make_float2(v0, v1);
                }
            }
        }
    }
}

// ---------------- fused LN + token-shift mix (float4 vectorized) --------------
__device__ __forceinline__ void ln_stats2_v4(float4 vT, float4 vP, bool hasP,
                                             float& mnT, float& invT,
                                             float& mnP, float& invP)
{
    float sT = vT.x + vT.y + vT.z + vT.w;
    float s2T = vT.x * vT.x + vT.y * vT.y + vT.z * vT.z + vT.w * vT.w;
    float sP = 0.f, s2P = 0.f;
    if (hasP) {
        sP = vP.x + vP.y + vP.z + vP.w;
        s2P = vP.x * vP.x + vP.y * vP.y + vP.z * vP.z + vP.w * vP.w;
    }
#pragma unroll
    for (int o = 16; o > 0; o >>= 1) {
        sT  += __shfl_down_sync(0xffffffffu, sT,  o);
        s2T += __shfl_down_sync(0xffffffffu, s2T, o);
        sP  += __shfl_down_sync(0xffffffffu, sP,  o);
        s2P += __shfl_down_sync(0xffffffffu, s2P, o);
    }
    __shared__ float sh[4][8];
    int warp = threadIdx.x >> 5, lane = threadIdx.x & 31;
    if (lane == 0) { sh[0][warp] = sT; sh[1][warp] = s2T; sh[2][warp] = sP; sh[3][warp] = s2P; }
    __syncthreads();
    float tT = 0.f, t2T = 0.f, tP = 0.f, t2P = 0.f;
#pragma unroll
    for (int i = 0; i < 8; i++) {
        tT += sh[0][i]; t2T += sh[1][i]; tP += sh[2][i]; t2P += sh[3][i];
    }
    mnT = tT * (1.f / CH);
    invT = rsqrtf(fmaxf(t2T * (1.f / CH) - mnT * mnT, 0.f) + 1e-5f);
    mnP = tP * (1.f / CH);
    invP = rsqrtf(fmaxf(t2P * (1.f / CH) - mnP * mnP, 0.f) + 1e-5f);
}

__global__ void ln_mix_time(const float* __restrict__ x,
                            const float* __restrict__ w, const float* __restrict__ b,
                            const float* __restrict__ mk, const float* __restrict__ mv,
                            const float* __restrict__ mr,
                            __half* __restrict__ xk, __half* __restrict__ xv,
                            __half* __restrict__ xr)
{
    const int row = blockIdx.x;
    const bool hasP = (row & (SEQ - 1)) != 0;
    const float* xT = x + (size_t)row * CH;
    const float* xP = xT - CH;
    const int i = threadIdx.x * 4;

    float4 vT = *(const float4*)(xT + i);
    float4 vP = hasP ? *(const float4*)(xP + i) : make_float4(0.f, 0.f, 0.f, 0.f);
    float mnT, invT, mnP, invP;
    ln_stats2_v4(vT, vP, hasP, mnT, invT, mnP, invP);

    float4 wv = *(const float4*)(w + i);
    float4 bv = *(const float4*)(b + i);
    float hT[4], hP[4];
    const float* pT = &vT.x; const float* pP = &vP.x;
    const float* pw = &wv.x; const float* pb = &bv.x;
#pragma unroll
    for (int q = 0; q < 4; q++) {
        hT[q] = (pT[q] - mnT) * invT * pw[q] + pb[q];
        hP[q] = hasP ? (pP[q] - mnP) * invP * pw[q] + pb[q] : 0.f;
    }
    const size_t e = (size_t)row * CH + i;
    float4 m;
    const float* pm;
    m = *(const float4*)(mk + i); pm = &m.x;
    store_h4(xk, e, hT[0]*pm[0]+hP[0]*(1.f-pm[0]), hT[1]*pm[1]+hP[1]*(1.f-pm[1]),
                   hT[2]*pm[2]+hP[2]*(1.f-pm[2]), hT[3]*pm[3]+hP[3]*(1.f-pm[3]));
    m = *(const float4*)(mv + i); pm = &m.x;
    store_h4(xv, e, hT[0]*pm[0]+hP[0]*(1.f-pm[0]), hT[1]*pm[1]+hP[1]*(1.f-pm[1]),
                   hT[2]*pm[2]+hP[2]*(1.f-pm[2]), hT[3]*pm[3]+hP[3]*(1.f-pm[3]));
    m = *(const float4*)(mr + i); pm = &m.x;
    store_h4(xr, e, hT[0]*pm[0]+hP[0]*(1.f-pm[0]), hT[1]*pm[1]+hP[1]*(1.f-pm[1]),
                   hT[2]*pm[2]+hP[2]*(1.f-pm[2]), hT[3]*pm[3]+hP[3]*(1.f-pm[3]));
}

__global__ void ln_mix_chan(const float* __restrict__ x,
                            const float* __restrict__ w, const float* __restrict__ b,
                            const float* __restrict__ mk, const float* __restrict__ mr,
                            __half* __restrict__ xk, __half* __restrict__ xr)
{
    const int row = blockIdx.x;
    const bool hasP = (row & (SEQ - 1)) != 0;
    const float* xT = x + (size_t)row * CH;
    const float* xP = xT - CH;
    const int i = threadIdx.x * 4;

    float4 vT = *(const float4*)(xT + i);
    float4 vP = hasP ? *(const float4*)(xP + i) : make_float4(0.f, 0.f, 0.f, 0.f);
    float mnT, invT, mnP, invP;
    ln_stats2_v4(vT, vP, hasP, mnT, invT, mnP, invP);

    float4 wv = *(const float4*)(w + i);
    float4 bv = *(const float4*)(b + i);
    float hT[4], hP[4];
    const float* pT = &vT.x; const float* pP = &vP.x;
    const float* pw = &wv.x; const float* pb = &bv.x;
#pragma unroll
    for (int q = 0; q < 4; q++) {
        hT[q] = (pT[q] - mnT) * invT * pw[q] + pb[q];
        hP[q] = hasP ? (pP[q] - mnP) * invP * pw[q] + pb[q] : 0.f;
    }
    const size_t e = (size_t)row * CH + i;
    float4 m;
    const float* pm;
    m = *(const float4*)(mk + i); pm = &m.x;
    store_h4(xk, e, hT[0]*pm[0]+hP[0]*(1.f-pm[0]), hT[1]*pm[1]+hP[1]*(1.f-pm[1]),
                   hT[2]*pm[2]+hP[2]*(1.f-pm[2]), hT[3]*pm[3]+hP[3]*(1.f-pm[3]));
    m = *(const float4*)(mr + i); pm = &m.x;
    store_h4(xr, e, hT[0]*pm[0]+hP[0]*(1.f-pm[0]), hT[1]*pm[1]+hP[1]*(1.f-pm[1]),
                   hT[2]*pm[2]+hP[2]*(1.f-pm[2]), hT[3]*pm[3]+hP[3]*(1.f-pm[3]));
}

// ---------------- layernorm (embed + final), float4 vectorized ----------------
__device__ __forceinline__ void ln_stats_v4(float4 v, float& mean, float& inv)
{
    float s = v.x + v.y + v.z + v.w;
    float s2 = v.x * v.x + v.y * v.y + v.z * v.z + v.w * v.w;
#pragma unroll
    for (int o = 16; o > 0; o >>= 1) {
        s  += __shfl_down_sync(0xffffffffu, s,  o);
        s2 += __shfl_down_sync(0xffffffffu, s2, o);
    }
    __shared__ float sh[2][8];
    int warp = threadIdx.x >> 5, lane = threadIdx.x & 31;
    if (lane == 0) { sh[0][warp] = s; sh[1][warp] = s2; }
    __syncthreads();
    float tot = 0.f, tot2 = 0.f;
#pragma unroll
    for (int i = 0; i < 8; i++) { tot += sh[0][i]; tot2 += sh[1][i]; }
    mean = tot * (1.f / CH);
    float var = tot2 * (1.f / CH) - mean * mean;
    inv = rsqrtf(fmaxf(var, 0.f) + 1e-5f);
}

__global__ void ln_rows_h(const float* __restrict__ in, __half* __restrict__ oh,
                          const float* __restrict__ w, const float* __restrict__ b)
{
    const size_t row = blockIdx.x;
    const int i = threadIdx.x * 4;
    float4 v = *(const float4*)(in + row * CH + i);
    float mean, inv;
    ln_stats_v4(v, mean, inv);
    float4 wv = *(const float4*)(w + i);
    float4 bv = *(const float4*)(b + i);
    store_h4(oh, row * CH + i,
             (v.x - mean) * inv * wv.x + bv.x,
             (v.y - mean) * inv * wv.y + bv.y,
             (v.z - mean) * inv * wv.z + bv.z,
             (v.w - mean) * inv * wv.w + bv.w);
}

__global__ void embed_ln0(const int* __restrict__ idx, const float* __restrict__ emb,
                          const float* __restrict__ w, const float* __restrict__ b,
                          float* __restrict__ out)
{
    int tok = idx[blockIdx.x];
    const int i = threadIdx.x * 4;
    float4 v = *(const float4*)(emb + (size_t)tok * CH + i);
    float mean, inv;
    ln_stats_v4(v, mean, inv);
    float4 wv = *(const float4*)(w + i);
    float4 bv = *(const float4*)(b + i);
    float4 o;
    o.x = (v.x - mean) * inv * wv.x + bv.x;
    o.y = (v.y - mean) * inv * wv.y + bv.y;
    o.z = (v.z - mean) * inv * wv.z + bv.z;
    o.w = (v.w - mean) * inv * wv.w + bv.w;
    *(float4*)(out + (size_t)blockIdx.x * CH + i) = o;
}

// ================= segmented WKV (3 passes) ===================================
__global__ void wkv_p1(const float* __restrict__ td,
                       const float* __restrict__ k, const float* __restrict__ v)
{
    int gid = blockIdx.x * 256 + threadIdx.x;
    if (gid >= WS * BC) return;
    int c  = gid % CH;
    int bs = gid / CH;
    int b  = bs & (BATCH - 1);
    int s  = bs / BATCH;
    float w = -__expf(td[c]);
    const float* kp = k + ((size_t)b * SEQ + (size_t)s * WL) * CH + c;
    const float* vp = v + ((size_t)b * SEQ + (size_t)s * WL) * CH + c;
    float a = 0.f, bb = 0.f, p = -1e38f;
#pragma unroll 4
    for (int t = 0; t < WL; t++) {
        float kt = kp[(size_t)t * CH];
        float vt = vp[(size_t)t * CH];
        float ww2 = p + w;
        float q2  = fmaxf(ww2, kt);
        float e1  = __expf(ww2 - q2);
        float e2  = __expf(kt - q2);
        a  = e1 * a  + e2 * vt;
        bb = e1 * bb + e2;
        p  = q2;
    }
    int slot = s * BC + b * CH + c;
    g_sa[slot] = a; g_sb[slot] = bb; g_sp[slot] = p;
}

__global__ void wkv_p2(const float* __restrict__ td)
{
    int gid = blockIdx.x * 256 + threadIdx.x;
    if (gid >= BC) return;
    int c = gid % CH;
    float w  = -__expf(td[c]);
    float wL = w * (float)WL;
    float a = 0.f, bb = 0.f, p = -1e38f;
    for (int s = 0; s < WS; s++) {
        int slot = s * BC + gid;
        g_ia[slot] = a; g_ib[slot] = bb; g_ip[slot] = p;
        float pin = p + wL;
        float pl = g_sp[slot];
        float pn = fmaxf(pin, pl);
        float e1 = __expf(pin - pn);
        float e2 = __expf(pl - pn);
        a  = e1 * a  + e2 * g_sa[slot];
        bb = e1 * bb + e2 * g_sb[slot];
        p  = pn;
    }
}

__global__ void wkv_p3(const float* __restrict__ td, const float* __restrict__ tf,
                       const float* __restrict__ k, const float* __restrict__ v,
                       const float* __restrict__ r, __half* __restrict__ gw)
{
    int gid = blockIdx.x * 256 + threadIdx.x;
    if (gid >= WS * BC) return;
    int c  = gid % CH;
    int bs = gid / CH;
    int b  = bs & (BATCH - 1);
    int s  = bs / BATCH;
    float w = -__expf(td[c]);
    float u = tf[c];
    const size_t base = ((size_t)b * SEQ + (size_t)s * WL) * CH + c;
    const float* kp = k + base;
    const float* vp = v + base;
    const float* rp = r + base;
    __half*      yp = gw + base;
    int slot = s * BC + b * CH + c;
    float a = g_ia[slot], bb = g_ib[slot], p = g_ip[slot];
#pragma unroll 4
    for (int t = 0; t < WL; t++) {
        float kt = kp[(size_t)t * CH];
        float vt = vp[(size_t)t * CH];
        float rt = rp[(size_t)t * CH];
        float ww = u + kt;
        float q  = fmaxf(p, ww);
        float e1 = __expf(p - q);
        float e2 = __expf(ww - q);
        float y  = (e1 * a + e2 * vt) / (e1 * bb + e2);
        yp[(size_t)t * CH] = __float2half_rn(y / (1.f + __expf(-rt)));
        float ww2 = p + w;
        float q2  = fmaxf(ww2, kt);
        float e1b = __expf(ww2 - q2);
        float e2b = __expf(kt - q2);
        a  = e1b * a  + e2b * vt;
        bb = e1b * bb + e2b;
        p  = q2;
    }
}

// ---------------- host orchestration ------------------------------------------
static GJob mkjob(const __half* A, const __half* B, float* C, __half* Ch,
                  const float* Res, const float* Mul, int N, int K,
                  int epi, int base, int tileN)
{
    GJob j;
    j.A = A; j.B = B; j.C = C; j.Ch = Ch; j.Res = Res; j.Mul = Mul;
    j.N = N; j.K = K; j.epi = epi; j.ntx = N / tileN; j.base = base;
    return j;
}

extern "C" void kernel_launch(void* const* d_in, const int* in_sizes, int n_in,
                              void* d_out, int out_size)
{
    (void)in_sizes; (void)n_in; (void)out_size;

    const int*   idx        = (const int*)  d_in[0];
    const float* emb        = (const float*)d_in[1];
    const float* ln0_w      = (const float*)d_in[2];
    const float* ln0_b      = (const float*)d_in[3];
    const float* ln1_w      = (const float*)d_in[4];
    const float* ln1_b      = (const float*)d_in[5];
    const float* ln2_w      = (const float*)d_in[6];
    const float* ln2_b      = (const float*)d_in[7];
    const float* time_decay = (const float*)d_in[8];
    const float* time_first = (const float*)d_in[9];
    const float* tmk        = (const float*)d_in[10];
    const float* tmv        = (const float*)d_in[11];
    const float* tmr        = (const float*)d_in[12];
    const float* att_Wk     = (const float*)d_in[13];
    const float* att_Wv     = (const float*)d_in[14];
    const float* att_Wr     = (const float*)d_in[15];
    const float* att_Wo     = (const float*)d_in[16];
    const float* fmk        = (const float*)d_in[17];
    const float* fmr        = (const float*)d_in[18];
    const float* ffn_Wk     = (const float*)d_in[19];
    const float* ffn_Wr     = (const float*)d_in[20];
    const float* ffn_Wv     = (const float*)d_in[21];
    const float* ln_out_w   = (const float*)d_in[22];
    const float* ln_out_b   = (const float*)d_in[23];
    const float* head_w     = (const float*)d_in[24];
    float* out = (float*)d_out;

    cudaFuncSetAttribute(gemm_w, cudaFuncAttributeMaxDynamicSharedMemorySize, W_SMEM);
    cudaFuncSetAttribute(gemm_n, cudaFuncAttributeMaxDynamicSharedMemorySize, N_SMEM);

    float *x, *kb, *vb, *rb, *rrb;
    cudaGetSymbolAddress((void**)&x,    g_x);
    cudaGetSymbolAddress((void**)&kb,   g_k);
    cudaGetSymbolAddress((void**)&vb,   g_v);
    cudaGetSymbolAddress((void**)&rb,   g_r);
    cudaGetSymbolAddress((void**)&rrb,  g_rr);

    __half *wp, *xk, *xv, *xr, *gw, *hh, *kk;
    cudaGetSymbolAddress((void**)&wp, g_w);
    cudaGetSymbolAddress((void**)&xk, g_xk);
    cudaGetSymbolAddress((void**)&xv, g_xv);
    cudaGetSymbolAddress((void**)&xr, g_xr);
    cudaGetSymbolAddress((void**)&gw, g_gw);
    cudaGetSymbolAddress((void**)&hh, g_hh);
    cudaGetSymbolAddress((void**)&kk, g_kk);

    // ---- single-launch weight conversion ----
    {
        CvtJobs cj;
        cj.src[0] = att_Wk; cj.dst[0] = wp + OW_ATTK; cj.n4[0] = (int)(6 * CCH / 4);
        cj.src[1] = att_Wv; cj.dst[1] = wp + OW_ATTV; cj.n4[1] = (int)(6 * CCH / 4);
        cj.src[2] = att_Wr; cj.dst[2] = wp + OW_ATTR; cj.n4[2] = (int)(6 * CCH / 4);
        cj.src[3] = att_Wo; cj.dst[3] = wp + OW_ATTO; cj.n4[3] = (int)(6 * CCH / 4);
        cj.src[4] = ffn_Wk; cj.dst[4] = wp + OW_FK;   cj.n4[4] = (int)(6 * FCH / 4);
        cj.src[5] = ffn_Wv; cj.dst[5] = wp + OW_FV;   cj.n4[5] = (int)(6 * FCH / 4);
        cj.src[6] = ffn_Wr; cj.dst[6] = wp + OW_FR;   cj.n4[6] = (int)(6 * CCH / 4);
        cj.src[7] = head_w; cj.dst[7] = wp + OW_HEAD; cj.n4[7] = (int)((size_t)VOCAB * CH / 4);
        dim3 g(1024, 8);
        cvt_all<<<g, 256>>>(cj);
    }

    const int TN_CC = (NROWS / 128) * (CH / 128);   // 256 narrow tiles
    const int TW_FF = (NROWS / 128) * (FF / 256);   // 512 wide tiles
    const int TW_CC = (NROWS / 128) * (CH / 256);   // 128 wide tiles

    embed_ln0<<<NROWS, 256>>>(idx, emb, ln0_w, ln0_b, x);

    for (int i = 0; i < NLAYER; i++) {
        size_t oc = (size_t)i * CH;
        const __half* Wk = wp + OW_ATTK + (size_t)i * CCH;
        const __half* Wv = wp + OW_ATTV + (size_t)i * CCH;
        const __half* Wr = wp + OW_ATTR + (size_t)i * CCH;
        const __half* Wo = wp + OW_ATTO + (size_t)i * CCH;
        const __half* Fk = wp + OW_FK   + (size_t)i * FCH;
        const __half* Fv = wp + OW_FV   + (size_t)i * FCH;
        const __half* Fr = wp + OW_FR   + (size_t)i * CCH;

        // ---- TimeMix ----
        ln_mix_time<<<NROWS, 256>>>(x, ln1_w + oc, ln1_b + oc,
                                    tmk + oc, tmv + oc, tmr + oc, xk, xv, xr);
        {
            GJobs j;
            j.njobs = 3;
            j.j[0] = mkjob(xk, Wk, kb, nullptr, nullptr, nullptr, CH, CH, EPI_NONE, 0, 128);
            j.j[1] = mkjob(xv, Wv, vb, nullptr, nullptr, nullptr, CH, CH, EPI_NONE, TN_CC, 128);
            j.j[2] = mkjob(xr, Wr, rb, nullptr, nullptr, nullptr, CH, CH, EPI_NONE, 2 * TN_CC, 128);
            gemm_n<<<3 * TN_CC, 256, N_SMEM>>>(j);
        }
        wkv_p1<<<WS * BC / 256, 256>>>(time_decay + oc, kb, vb);
        wkv_p2<<<BC / 256, 256>>>(time_decay + oc);
        wkv_p3<<<WS * BC / 256, 256>>>(time_decay + oc, time_first + oc, kb, vb, rb, gw);
        {
            GJobs j;
            j.njobs = 1;
            j.j[0] = mkjob(gw, Wo, x, nullptr, x, nullptr, CH, CH, EPI_ADD, 0, 128);
            gemm_n<<<TN_CC, 256, N_SMEM>>>(j);
        }

        // ---- ChannelMix ----
        ln_mix_chan<<<NROWS, 256>>>(x, ln2_w + oc, ln2_b + oc, fmk + oc, fmr + oc, xk, xr);
        {
            GJobs j;
            j.njobs = 2;
            j.j[0] = mkjob(xk, Fk, nullptr, kk, nullptr, nullptr, FF, CH, EPI_RELUSQ, 0, 256);
            j.j[1] = mkjob(xr, Fr, rrb, nullptr, nullptr, nullptr, CH, CH, EPI_SIGMOID, TW_FF, 256);
            gemm_w<<<TW_FF + TW_CC, 512, W_SMEM>>>(j);
        }
        {
            GJobs j;
            j.njobs = 1;
            j.j[0] = mkjob(kk, Fv, x, nullptr, x, rrb, CH, FF, EPI_ADD_MUL, 0, 128);
            gemm_n<<<TN_CC, 256, N_SMEM>>>(j);
        }
    }

    // final LN + head projection — EXPERIMENT: narrow tiles (2 CTAs/SM)
    ln_rows_h<<<NROWS, 256>>>(x, hh, ln_out_w, ln_out_b);
    {
        GJobs j;
        j.njobs = 1;
        j.j[0] = mkjob(hh, wp + OW_HEAD, out, nullptr, nullptr, nullptr,
                       VOCAB, CH, EPI_NONE, 0, 128);
        gemm_n<<<(NROWS / 128) * (VOCAB / 128), 256, N_SMEM>>>(j);
    }
}